// round 7
// baseline (speedup 1.0000x reference)
#include <cuda_runtime.h>

#define H_IN 512
#define W_IN 512
#define H_OUT 512
#define W_OUT 512
#define BC 96            // 32 batch * 3 channels
#define HW (H_IN * W_IN) // 262144
#define BC_CHUNK 8
#define NCHUNK (BC / BC_CHUNK)   // 12
// LDG return-BW model: scalar 4-load path = 4*max(1,s) cycles, float4-pair
// = 2*max(4,s)+fixups, s = tap spacing = rho/77.8 px. Crossover s~2.5 -> j~410.
#define INNER_J 416

// max_r = log(sqrt(512^2+512^2)/2 * 2) = log(512*sqrt(2))
#define MAX_R 6.58489821532f
#define PI_F 3.14159265358979f

// Precomputed map: weights (mask folded in) and the two row-tap offsets.
__device__ float4 g_w[HW];   // wdd, wdu, wud, wuu
__device__ int2   g_o[HW];   // o_dd (= ydi*512+xdi), o_ud (= yui*512+xdi); (0,0) if masked

__global__ __launch_bounds__(256) void map_kernel()
{
    int pix = blockIdx.x * blockDim.x + threadIdx.x;
    if (pix >= HW) return;

    int i = pix >> 9;    // theta index
    int j = pix & 511;   // r index

    float rv = (float)j * MAX_R / (float)W_OUT;
    float radius = expf(rv);

    float ang = (float)(2 * i) * PI_F / (float)H_OUT;
    float s, c;
    sincosf(ang, &s, &c);

    float X = 256.0f + radius * c;
    float Y = 256.0f - radius * s;

    bool inb = (X >= 0.0f && X < (float)H_IN && Y >= 0.0f && Y < (float)W_IN);
    float mask = inb ? 1.0f : 0.0f;

    int ydi = (int)Y;  ydi = min(max(ydi, 0), H_IN - 1);
    int xdi = (int)X;  xdi = min(max(xdi, 0), W_IN - 1);
    int yui = min(ydi + 1, H_IN - 1);
    int xui = min(xdi + 1, W_IN - 1);

    float yd = Y - (float)ydi;
    float yu = Y - (float)yui;
    float xd = X - (float)xdi;
    float xu = X - (float)xui;

    float yd2 = yd * yd, yu2 = yu * yu, xd2 = xd * xd, xu2 = xu * xu;
    float dd = yd2 + xd2;
    float du = yd2 + xu2;
    float ud = yu2 + xd2;
    float uu = yu2 + xu2;
    float total = dd + du + ud + uu;
    float inv = mask / total;

    g_w[pix] = make_float4(dd * inv, du * inv, ud * inv, uu * inv);
    // Masked pixels: weights all zero -> loaded values irrelevant. Point taps
    // at offset 0 so dead lanes broadcast ONE line instead of scattering.
    if (inb) {
        g_o[pix] = make_int2(ydi * W_IN + xdi, yui * W_IN + xdi);
    } else {
        g_o[pix] = make_int2(0, 0);
    }
}

__global__ __launch_bounds__(128, 12) void gather_kernel(
    const float* __restrict__ in, float* __restrict__ out)
{
    int pix = blockIdx.x * 128 + threadIdx.x;
    int bc0 = blockIdx.y * BC_CHUNK;

    float4 w = __ldg(&g_w[pix]);
    int2 o = __ldg(&g_o[pix]);

    int j = pix & 511;
    int d1 = ((o.x & 511) < W_IN - 1) ? 1 : 0;
    int o_du = o.x + d1;
    int o_uu = o.y + d1;

    const float* src = in + (size_t)bc0 * HW;
    float* dst = out + (size_t)bc0 * HW + pix;

    if (j < INNER_J) {
        // Small/mid radii: four scalar loads are return-BW-optimal and the
        // gathered annulus is hot in L1/L2 -> default caching.
#pragma unroll 4
        for (int k = 0; k < BC_CHUNK; ++k) {
            float vdd = __ldg(src + o.x);
            float vdu = __ldg(src + o_du);
            float vud = __ldg(src + o.y);
            float vuu = __ldg(src + o_uu);
            float r = w.x * vdd + w.y * vdu + w.z * vud + w.w * vuu;
            *dst = r;
            src += HW;
            dst += HW;
        }
    } else {
        // Large radii: one float4 per row; lanes touch private lines with ~no
        // L1 reuse -> __ldcg to skip L1 allocation and keep it for the inner
        // band's hot working set. Masked lanes (o==0) broadcast a single line.
        int sel = o.x & 3;
        int base_d = o.x & ~3;
        int base_u = o.y & ~3;
        bool s1 = (sel == 1), s2 = (sel == 2), s3 = (sel == 3);

#pragma unroll 4
        for (int k = 0; k < BC_CHUNK; ++k) {
            float4 fd = __ldcg(reinterpret_cast<const float4*>(src + base_d));
            float4 fu = __ldcg(reinterpret_cast<const float4*>(src + base_u));

            float sdu = 0.0f, suu = 0.0f;
            if (s3) {
                sdu = __ldcg(src + o_du);
                suu = __ldcg(src + o_uu);
            }

            float vdd = s1 ? fd.y : fd.x;  vdd = s2 ? fd.z : vdd;  vdd = s3 ? fd.w : vdd;
            float vud = s1 ? fu.y : fu.x;  vud = s2 ? fu.z : vud;  vud = s3 ? fu.w : vud;
            float vdu = s1 ? fd.z : fd.y;  vdu = s2 ? fd.w : vdu;  vdu = s3 ? sdu  : vdu;
            float vuu = s1 ? fu.z : fu.y;  vuu = s2 ? fu.w : vuu;  vuu = s3 ? suu  : vuu;

            float r = w.x * vdd + w.y * vdu + w.z * vud + w.w * vuu;
            *dst = r;
            src += HW;
            dst += HW;
        }
    }
}

extern "C" void kernel_launch(void* const* d_in, const int* in_sizes, int n_in,
                              void* d_out, int out_size)
{
    const float* in = (const float*)d_in[0];
    float* out = (float*)d_out;

    map_kernel<<<HW / 256, 256>>>();

    dim3 grid(HW / 128, NCHUNK);
    gather_kernel<<<grid, 128>>>(in, out);
}

// round 8
// speedup vs baseline: 1.0004x; 1.0004x over previous
#include <cuda_runtime.h>

#define H_IN 512
#define W_IN 512
#define H_OUT 512
#define W_OUT 512
#define BC 96            // 32 batch * 3 channels
#define HW (H_IN * W_IN) // 262144
#define BC_CHUNK 8
#define NCHUNK (BC / BC_CHUNK)   // 12
// LDG return-BW model: scalar 4-load path = 4*max(1,s) cycles, float4-pair
// = 2*max(4,s)+fixups, s = tap spacing = rho/77.8 px. Crossover s~2.5 -> j~410.
#define INNER_J 416

// max_r = log(sqrt(512^2+512^2)/2 * 2) = log(512*sqrt(2))
#define MAX_R 6.58489821532f
#define PI_F 3.14159265358979f

// Precomputed map: weights (mask folded in) and the two row-tap offsets.
__device__ float4 g_w[HW];   // wdd, wdu, wud, wuu
__device__ int2   g_o[HW];   // o_dd (= ydi*512+xdi), o_ud (= yui*512+xdi); (0,0) if masked

__global__ __launch_bounds__(256) void map_kernel()
{
    int pix = blockIdx.x * blockDim.x + threadIdx.x;
    if (pix >= HW) return;

    int i = pix >> 9;    // theta index
    int j = pix & 511;   // r index

    float rv = (float)j * MAX_R / (float)W_OUT;
    float radius = expf(rv);

    float ang = (float)(2 * i) * PI_F / (float)H_OUT;
    float s, c;
    sincosf(ang, &s, &c);

    float X = 256.0f + radius * c;
    float Y = 256.0f - radius * s;

    bool inb = (X >= 0.0f && X < (float)H_IN && Y >= 0.0f && Y < (float)W_IN);
    float mask = inb ? 1.0f : 0.0f;

    int ydi = (int)Y;  ydi = min(max(ydi, 0), H_IN - 1);
    int xdi = (int)X;  xdi = min(max(xdi, 0), W_IN - 1);
    int yui = min(ydi + 1, H_IN - 1);
    int xui = min(xdi + 1, W_IN - 1);

    float yd = Y - (float)ydi;
    float yu = Y - (float)yui;
    float xd = X - (float)xdi;
    float xu = X - (float)xui;

    float yd2 = yd * yd, yu2 = yu * yu, xd2 = xd * xd, xu2 = xu * xu;
    float dd = yd2 + xd2;
    float du = yd2 + xu2;
    float ud = yu2 + xd2;
    float uu = yu2 + xu2;
    float total = dd + du + ud + uu;
    float inv = mask / total;

    g_w[pix] = make_float4(dd * inv, du * inv, ud * inv, uu * inv);
    // Masked pixels: weights all zero -> loaded values irrelevant. Point taps
    // at offset 0 so dead lanes broadcast ONE line instead of scattering.
    if (inb) {
        g_o[pix] = make_int2(ydi * W_IN + xdi, yui * W_IN + xdi);
    } else {
        g_o[pix] = make_int2(0, 0);
    }
}

__global__ __launch_bounds__(128, 12) void gather_kernel(
    const float* __restrict__ in, float* __restrict__ out)
{
    int pix = blockIdx.x * 128 + threadIdx.x;
    int bc0 = blockIdx.y * BC_CHUNK;

    float4 w = __ldg(&g_w[pix]);
    int2 o = __ldg(&g_o[pix]);

    int j = pix & 511;
    int d1 = ((o.x & 511) < W_IN - 1) ? 1 : 0;
    int o_du = o.x + d1;
    int o_uu = o.y + d1;

    const float* src = in + (size_t)bc0 * HW;
    float* dst = out + (size_t)bc0 * HW + pix;

    if (j < INNER_J) {
        // Small/mid radii: four scalar loads are return-BW-optimal and the
        // gathered annulus is hot in L1/L2 -> default caching.
#pragma unroll 4
        for (int k = 0; k < BC_CHUNK; ++k) {
            float vdd = __ldg(src + o.x);
            float vdu = __ldg(src + o_du);
            float vud = __ldg(src + o.y);
            float vuu = __ldg(src + o_uu);
            float r = w.x * vdd + w.y * vdu + w.z * vud + w.w * vuu;
            *dst = r;
            src += HW;
            dst += HW;
        }
    } else {
        // Large radii: one float4 per row; lanes touch private lines with ~no
        // L1 reuse -> __ldcg to skip L1 allocation and keep it for the inner
        // band's hot working set. Masked lanes (o==0) broadcast a single line.
        int sel = o.x & 3;
        int base_d = o.x & ~3;
        int base_u = o.y & ~3;
        bool s1 = (sel == 1), s2 = (sel == 2), s3 = (sel == 3);

#pragma unroll 4
        for (int k = 0; k < BC_CHUNK; ++k) {
            float4 fd = __ldcg(reinterpret_cast<const float4*>(src + base_d));
            float4 fu = __ldcg(reinterpret_cast<const float4*>(src + base_u));

            float sdu = 0.0f, suu = 0.0f;
            if (s3) {
                sdu = __ldcg(src + o_du);
                suu = __ldcg(src + o_uu);
            }

            float vdd = s1 ? fd.y : fd.x;  vdd = s2 ? fd.z : vdd;  vdd = s3 ? fd.w : vdd;
            float vud = s1 ? fu.y : fu.x;  vud = s2 ? fu.z : vud;  vud = s3 ? fu.w : vud;
            float vdu = s1 ? fd.z : fd.y;  vdu = s2 ? fd.w : vdu;  vdu = s3 ? sdu  : vdu;
            float vuu = s1 ? fu.z : fu.y;  vuu = s2 ? fu.w : vuu;  vuu = s3 ? suu  : vuu;

            float r = w.x * vdd + w.y * vdu + w.z * vud + w.w * vuu;
            *dst = r;
            src += HW;
            dst += HW;
        }
    }
}

extern "C" void kernel_launch(void* const* d_in, const int* in_sizes, int n_in,
                              void* d_out, int out_size)
{
    const float* in = (const float*)d_in[0];
    float* out = (float*)d_out;

    map_kernel<<<HW / 256, 256>>>();

    dim3 grid(HW / 128, NCHUNK);
    gather_kernel<<<grid, 128>>>(in, out);
}

// round 9
// speedup vs baseline: 1.0600x; 1.0596x over previous
#include <cuda_runtime.h>

#define H_IN 512
#define W_IN 512
#define H_OUT 512
#define W_OUT 512
#define BC 96            // 32 batch * 3 channels
#define HW (H_IN * W_IN) // 262144
#define BC_CHUNK 12
#define NCHUNK (BC / BC_CHUNK)   // 8
// LDG return-BW model: scalar 4-load path = 4*max(1,s) wavefronts, float4-pair
// = 2*max(4,s)+fixups, s = tap spacing = rho/77.8 px. Crossover s~2.5 -> j~410.
#define INNER_J 416

// max_r = log(sqrt(512^2+512^2)/2 * 2) = log(512*sqrt(2))
#define MAX_R 6.58489821532f
#define PI_F 3.14159265358979f

__global__ __launch_bounds__(128, 8) void gather_kernel(
    const float* __restrict__ in, float* __restrict__ out)
{
    int pix = blockIdx.x * 128 + threadIdx.x;
    int bc0 = blockIdx.y * BC_CHUNK;

    // ---- inline map computation (MUFU pipe is idle; amortized over BC_CHUNK) ----
    int i = pix >> 9;    // theta index
    int j = pix & 511;   // r index

    float rv = (float)j * MAX_R / (float)W_OUT;
    float radius = expf(rv);

    float ang = (float)(2 * i) * PI_F / (float)H_OUT;
    float sn, cs;
    sincosf(ang, &sn, &cs);

    float X = 256.0f + radius * cs;
    float Y = 256.0f - radius * sn;

    bool inb = (X >= 0.0f && X < (float)H_IN && Y >= 0.0f && Y < (float)W_IN);
    float mask = inb ? 1.0f : 0.0f;

    int ydi = (int)Y;  ydi = min(max(ydi, 0), H_IN - 1);
    int xdi = (int)X;  xdi = min(max(xdi, 0), W_IN - 1);
    int yui = min(ydi + 1, H_IN - 1);
    int xui = min(xdi + 1, W_IN - 1);

    float yd = Y - (float)ydi;
    float yu = Y - (float)yui;
    float xd = X - (float)xdi;
    float xu = X - (float)xui;

    float yd2 = yd * yd, yu2 = yu * yu, xd2 = xd * xd, xu2 = xu * xu;
    float dd = yd2 + xd2;
    float du = yd2 + xu2;
    float ud = yu2 + xd2;
    float uu = yu2 + xu2;
    float total = dd + du + ud + uu;
    float inv = mask / total;

    float4 w = make_float4(dd * inv, du * inv, ud * inv, uu * inv);

    // Masked pixels: weights all zero -> loaded values irrelevant. Point taps
    // at offset 0 so dead lanes broadcast ONE cache line instead of scattering.
    int2 o;
    if (inb) {
        o = make_int2(ydi * W_IN + xdi, yui * W_IN + xdi);
    } else {
        o = make_int2(0, 0);
    }

    int d1 = ((o.x & 511) < W_IN - 1) ? 1 : 0;
    int o_du = o.x + d1;
    int o_uu = o.y + d1;

    const float* src = in + (size_t)bc0 * HW;
    float* dst = out + (size_t)bc0 * HW + pix;

    if (j < INNER_J) {
        // Small/mid radii: four scalar loads are wavefront-optimal (1 line each
        // at small tap spacing) and the gathered annulus is hot in L1/L2.
#pragma unroll 4
        for (int k = 0; k < BC_CHUNK; ++k) {
            float vdd = __ldg(src + o.x);
            float vdu = __ldg(src + o_du);
            float vud = __ldg(src + o.y);
            float vuu = __ldg(src + o_uu);
            float r = w.x * vdd + w.y * vdu + w.z * vud + w.w * vuu;
            *dst = r;
            src += HW;
            dst += HW;
        }
    } else {
        // Large radii: lanes touch private lines; fewer load instructions win.
        // Masked lanes (o==0) broadcast a single line.
        int sel = o.x & 3;
        int base_d = o.x & ~3;
        int base_u = o.y & ~3;
        bool s1 = (sel == 1), s2 = (sel == 2), s3 = (sel == 3);

#pragma unroll 4
        for (int k = 0; k < BC_CHUNK; ++k) {
            float4 fd = __ldg(reinterpret_cast<const float4*>(src + base_d));
            float4 fu = __ldg(reinterpret_cast<const float4*>(src + base_u));

            float sdu = 0.0f, suu = 0.0f;
            if (s3) {
                sdu = __ldg(src + o_du);
                suu = __ldg(src + o_uu);
            }

            float vdd = s1 ? fd.y : fd.x;  vdd = s2 ? fd.z : vdd;  vdd = s3 ? fd.w : vdd;
            float vud = s1 ? fu.y : fu.x;  vud = s2 ? fu.z : vud;  vud = s3 ? fu.w : vud;
            float vdu = s1 ? fd.z : fd.y;  vdu = s2 ? fd.w : vdu;  vdu = s3 ? sdu  : vdu;
            float vuu = s1 ? fu.z : fu.y;  vuu = s2 ? fu.w : vuu;  vuu = s3 ? suu  : vuu;

            float r = w.x * vdd + w.y * vdu + w.z * vud + w.w * vuu;
            *dst = r;
            src += HW;
            dst += HW;
        }
    }
}

extern "C" void kernel_launch(void* const* d_in, const int* in_sizes, int n_in,
                              void* d_out, int out_size)
{
    const float* in = (const float*)d_in[0];
    float* out = (float*)d_out;

    dim3 grid(HW / 128, NCHUNK);
    gather_kernel<<<grid, 128>>>(in, out);
}